// round 16
// baseline (speedup 1.0000x reference)
#include <cuda_runtime.h>
#include <math.h>
#include <stdint.h>

// Problem constants: N_OBJ=1024, C_DET=8, C_SEG=4, H=W=28
#define C_DET 8
#define C_SEG 4
#define HW4 196            // 28*28/4 (float4 units)
#define N_OBJ 1024
#define OBJS 2             // objects per block
#define NPAIR (N_OBJ / OBJS)   // 512
#define RTHREADS 256
#define MAX_EDGES 64
#define NBLOCKS (NPAIR * C_DET)   // 4096
#define DET_BYTES (HW4 * 16)       // 3136
#define SEG_BYTES (C_SEG * HW4 * 16) // 12544
#define TX_BYTES (OBJS * (DET_BYTES + SEG_BYTES))  // 31360

// Global double accumulators: [c][0]=denom, [c][1..4]=A[c][s].
// Zero at module load; tail re-zeroes after reading -> replay-safe.
__device__ double g_acc[C_DET][5];
__device__ unsigned int g_count;   // ticket (acq_rel); reset by last block
__device__ float g_sink;           // DCE-blocker for L2 warm-up

__device__ __forceinline__ uint32_t smem_u32(const void* p) {
    uint32_t a;
    asm("{ .reg .u64 t; cvta.to.shared.u64 t, %1; cvt.u32.u64 %0, t; }"
        : "=r"(a) : "l"(p));
    return a;
}
__device__ __forceinline__ void bulk_g2s(uint32_t dst, const void* src,
                                         uint32_t bytes, uint32_t mbar) {
    asm volatile(
        "cp.async.bulk.shared::cta.global.mbarrier::complete_tx::bytes "
        "[%0], [%1], %2, [%3];"
        :: "r"(dst), "l"(src), "r"(bytes), "r"(mbar) : "memory");
}
__device__ __forceinline__ unsigned int ticket_acq_rel() {
    unsigned int old;
    asm volatile("atom.add.acq_rel.gpu.global.u32 %0, [%1], 1;"
                 : "=r"(old) : "l"(&g_count) : "memory");
    return old;
}
__device__ __forceinline__ double ld_cg_f64(const double* p) {
    double v;
    asm volatile("ld.global.cg.f64 %0, [%1];" : "=d"(v) : "l"(p));
    return v;
}

// TMA-path fused kernel: bulk-copy tiles into SMEM (bypasses the L1tex
// MSHR in-flight ceiling that clamped every LDG variant at ~4TB/s),
// compute from SMEM, publish via L2 double atomics, fence-free ticket tail.
__global__ __launch_bounds__(RTHREADS) void fused_kernel(
    const float4* __restrict__ det4,   // (N,C_DET,HW4) float4
    const float4* __restrict__ seg4,   // (N,C_DET,C_SEG,HW4) float4
    const float*  __restrict__ dcp,    // (N_OBJ, C_DET)
    const int*    __restrict__ edge_i, // int32
    const int*    __restrict__ edge_j,
    int n_edges,
    float* __restrict__ out)
{
    __shared__ __align__(128) float4 s_det[OBJS][HW4];
    __shared__ __align__(128) float4 s_seg[OBJS][C_SEG][HW4];
    __shared__ __align__(8) uint64_t s_mbar;
    __shared__ float s_stage[8];   // per-warp dot results (o*4+s)
    __shared__ float s_dn[OBJS];   // per-object denom

    const int c   = blockIdx.y;
    const int n0  = blockIdx.x * OBJS;
    const int tid = threadIdx.x;
    const int wid = tid >> 5;
    const int lid = tid & 31;

    const uint32_t mbar = smem_u32(&s_mbar);

    if (tid == 0) {
        asm volatile("mbarrier.init.shared.b64 [%0], 1;" :: "r"(mbar) : "memory");
    }
    __syncthreads();

    if (tid == 0) {
        asm volatile("mbarrier.arrive.expect_tx.shared.b64 _, [%0], %1;"
                     :: "r"(mbar), "r"((uint32_t)TX_BYTES) : "memory");
        #pragma unroll
        for (int o = 0; o < OBJS; o++) {
            const size_t m = (size_t)(n0 + o) * C_DET + c;
            bulk_g2s(smem_u32(&s_det[o][0]), det4 + m * HW4, DET_BYTES, mbar);
            bulk_g2s(smem_u32(&s_seg[o][0][0]), seg4 + m * (C_SEG * HW4), SEG_BYTES, mbar);
        }
    }

    // L2 warm-up for the tail (one block) — overlaps its own TMA wait.
    if (blockIdx.x == 0 && c == 0) {
        const float4* dcp4 = (const float4*)dcp;
        float acc2 = 0.0f;
        for (int i = tid; i < N_OBJ * C_DET / 4; i += RTHREADS) {
            const float4 v = __ldcg(dcp4 + i);
            acc2 += v.x + v.y + v.z + v.w;
        }
        if (tid < n_edges)
            acc2 += (float)(__ldcg(edge_i + tid) + __ldcg(edge_j + tid));
        if (tid == 0) g_sink = acc2;
    }

    // Wait for both tiles (parity 0; mbar re-inited every launch).
    {
        uint32_t done;
        asm volatile(
            "{\n\t.reg .pred p;\n\t"
            "mbarrier.try_wait.parity.acquire.cta.shared::cta.b64 p, [%1], 0;\n\t"
            "selp.b32 %0, 1, 0, p;\n\t}"
            : "=r"(done) : "r"(mbar) : "memory");
        if (!done) {
            asm volatile(
                "{\n\t.reg .pred P1;\n\t"
                "WAIT_LOOP:\n\t"
                "mbarrier.try_wait.parity.acquire.cta.shared::cta.b64 P1, [%0], 0, 0x989680;\n\t"
                "@P1 bra.uni WAIT_DONE;\n\t"
                "bra.uni WAIT_LOOP;\n\t"
                "WAIT_DONE:\n\t}"
                :: "r"(mbar) : "memory");
        }
    }

    // Compute from SMEM: warp (o = wid>>2, s = wid&3) does one dot product.
    {
        const int o = wid >> 2;
        const int s = wid & 3;
        float a = 0.0f, dn = 0.0f;
        #pragma unroll
        for (int it = 0; it < 7; it++) {
            const int q = lid + it * 32;
            if (q < HW4) {
                const float4 v = s_seg[o][s][q];
                const float4 d = s_det[o][q];
                a += d.x * v.x + d.y * v.y + d.z * v.z + d.w * v.w;
                if (s == 0) dn += (d.x + d.y) + (d.z + d.w);
            }
        }
        #pragma unroll
        for (int off = 16; off; off >>= 1) {
            a += __shfl_xor_sync(0xFFFFFFFFu, a, off);
            if (s == 0) dn += __shfl_xor_sync(0xFFFFFFFFu, dn, off);
        }
        if (lid == 0) {
            s_stage[wid] = a;
            if (s == 0) s_dn[o] = dn;
        }
    }
    __syncthreads();

    if (tid < 4)                       // A[c][s]: combine both objects
        atomicAdd(&g_acc[c][1 + tid], (double)(s_stage[tid] + s_stage[4 + tid]));
    if (tid == 4)                      // denom[c]
        atomicAdd(&g_acc[c][0], (double)(s_dn[0] + s_dn[1]));

    // ---------- Fence-free ticket ----------
    __shared__ unsigned int s_last;
    if (tid == 0)
        s_last = (ticket_acq_rel() == NBLOCKS - 1) ? 1u : 0u;
    __syncthreads();
    if (!s_last) return;
    if (tid == 0) g_count = 0;          // reset for next graph replay

    // ---------- Tail (last block, L2-warm data) ----------
    __shared__ double s_acc[C_DET][5];
    __shared__ float  s_w[C_DET];
    __shared__ float  s_red[RTHREADS / 32];
    __shared__ int    s_ei[MAX_EDGES], s_ej[MAX_EDGES];

    if (tid < n_edges) { s_ei[tid] = edge_i[tid]; s_ej[tid] = edge_j[tid]; }
    if (tid < C_DET * 5)
        ((double*)s_acc)[tid] = ld_cg_f64(((const double*)g_acc) + tid);
    __syncthreads();

    if (tid < C_DET * 5) ((double*)g_acc)[tid] = 0.0;   // replay reset

    if (tid < C_DET) {
        double acc = 0.0;
        for (int e = 0; e < n_edges; e++)
            if (s_ej[e] == tid)
                acc += s_acc[tid][1 + s_ei[e]] / s_acc[tid][0];
        s_w[tid] = (float)acc;
    }
    __syncthreads();

    float w[C_DET];
    #pragma unroll
    for (int k = 0; k < C_DET; k++) w[k] = s_w[k];

    const float4* dcp4 = (const float4*)dcp;
    float l = 0.0f;
    #pragma unroll
    for (int o = 0; o < N_OBJ / RTHREADS; o++) {
        const int obj = o * RTHREADS + tid;
        const float4 d0 = dcp4[obj * 2 + 0];
        const float4 d1 = dcp4[obj * 2 + 1];
        float p = d0.x * w[0] + d0.y * w[1] + d0.z * w[2] + d0.w * w[3]
                + d1.x * w[4] + d1.y * w[5] + d1.z * w[6] + d1.w * w[7];
        l += -fmaxf(logf(p), -100.0f);
    }

    #pragma unroll
    for (int off = 16; off; off >>= 1) l += __shfl_xor_sync(0xFFFFFFFFu, l, off);
    if (lid == 0) s_red[wid] = l;
    __syncthreads();

    if (tid == 0) {
        float v = 0.0f;
        #pragma unroll
        for (int i = 0; i < RTHREADS / 32; i++) v += s_red[i];
        out[0] = v / (float)N_OBJ;
    }
}

extern "C" void kernel_launch(void* const* d_in, const int* in_sizes, int n_in,
                              void* d_out, int out_size) {
    // metadata order: det_class_probs (f32), det_mask_probs (f32),
    //                 seg_mask_probs (f32), edge_i (i32), edge_j (i32)
    const float*  dcp = (const float*)d_in[0];
    const float4* det = (const float4*)d_in[1];
    const float4* seg = (const float4*)d_in[2];
    const int*    ei  = (const int*)d_in[3];
    const int*    ej  = (const int*)d_in[4];
    const int n_edges = in_sizes[3] < MAX_EDGES ? in_sizes[3] : MAX_EDGES;
    float* out = (float*)d_out;

    fused_kernel<<<dim3(NPAIR, C_DET), RTHREADS>>>(det, seg, dcp, ei, ej, n_edges, out);
}